// round 2
// baseline (speedup 1.0000x reference)
#include <cuda_runtime.h>
#include <math.h>

#define NCTA 128
#define NTHR 256
#define WID  1024
#define HID  256
#define NST  17
#define XD   273
#define TLEN 64
#define SUB  8
#define ROWH (WID/NCTA)   /* 8 hidden rows per CTA  */
#define ROWL (HID/NCTA)   /* 2 output rows per CTA  */

// smem layout sizes (floats)
#define SM_WH   (3*ROWH*WID)   /* 24576 */
#define SM_WL   (ROWL*WID)     /* 2048  */
#define SM_W0   (ROWH*XD)      /* 2184  */
#define SMEM_FLOATS (SM_WH + SM_WL + SM_W0 + WID + 280*3 + HID + 8 + 24 + 4 + 20 + 8)
#define SMEM_BYTES  (SMEM_FLOATS*4)

// ---------------- global communication state ----------------
__device__ __align__(128) float    g_z[2][WID];
__device__ __align__(128) float    g_dh[HID];
__device__ __align__(128) unsigned g_flags[NCTA];   // zero-init
__device__ __align__(128) unsigned g_gen_base;      // monotonic across replays

__device__ __forceinline__ void st_flag(unsigned* p, unsigned v)
{
    asm volatile("st.relaxed.gpu.global.b32 [%0], %1;" :: "l"(p), "r"(v) : "memory");
}

// all-to-all flag barrier: each CTA posts its flag, warp 0 of every CTA
// polls all 128 flags (>= gen handles the legal 1-barrier skew).
__device__ __forceinline__ void grid_barrier(unsigned gen)
{
    __syncthreads();
    const int tid = threadIdx.x;
    if (tid == 0) {
        __threadfence();
        st_flag(&g_flags[blockIdx.x], gen);
    }
    if (tid < 32) {
        const unsigned* p = g_flags + (tid << 2);
        unsigned a, b, c, d;
        for (;;) {
            asm volatile("ld.relaxed.gpu.global.v4.b32 {%0,%1,%2,%3}, [%4];"
                         : "=r"(a), "=r"(b), "=r"(c), "=r"(d) : "l"(p));
            bool ok = (a >= gen) & (b >= gen) & (c >= gen) & (d >= gen);
            if (__all_sync(0xffffffffu, ok)) break;
        }
        __threadfence();
    }
    __syncthreads();
}

__device__ __forceinline__ float sp_f(float x)   // softplus
{
    return fmaxf(x, 0.0f) + log1pf(expf(-fabsf(x)));
}

__device__ __forceinline__ float wred(float v)
{
    #pragma unroll
    for (int o = 16; o; o >>= 1) v += __shfl_xor_sync(0xffffffffu, v, o);
    return v;
}

__global__ void __launch_bounds__(NTHR, 1)
ode_kernel(const float* __restrict__ ts, const float* __restrict__ W0,
           const float* __restrict__ b0, const float* __restrict__ Wh,
           const float* __restrict__ bh, const float* __restrict__ Wl,
           const float* __restrict__ bl, const float* __restrict__ beta_W,
           const float* __restrict__ beta_b, const float* __restrict__ hvec,
           const float* __restrict__ scale, const float* __restrict__ y0_log,
           float* __restrict__ out)
{
    extern __shared__ float smem[];
    float* sWh    = smem;               // [3][ROWH][WID]
    float* sWl    = sWh + SM_WH;        // [ROWL][WID]
    float* sW0    = sWl + SM_WL;        // [ROWH][XD]
    float* sZ     = sW0 + SM_W0;        // [WID]  (16B aligned)
    float* sY     = sZ + WID;           // 280
    float* sStage = sY + 280;           // 280
    float* sKacc  = sStage + 280;       // 280
    float* sBetaW = sKacc + 280;        // 256
    float* sB0    = sBetaW + HID;       // 8
    float* sBh    = sB0 + ROWH;         // 24
    float* sBl    = sBh + 3*ROWH;       // 4
    float* sKst   = sBl + 4;            // 20
    float* sRed   = sKst + 20;          // 8

    const int tid  = threadIdx.x;
    const int cta  = blockIdx.x;
    const int wid  = tid >> 5;
    const int lane = tid & 31;

    // ---- one-time: weights -> smem ----
    #pragma unroll 1
    for (int l = 0; l < 3; l++) {
        const float4* src = (const float4*)(Wh + ((size_t)l * WID + (size_t)cta * ROWH) * WID);
        float4* dst = (float4*)(sWh + l * ROWH * WID);
        #pragma unroll
        for (int i = 0; i < (ROWH * WID / 4) / NTHR; i++)   // 8
            dst[tid + i * NTHR] = src[tid + i * NTHR];
    }
    {
        const float4* src = (const float4*)(Wl + (size_t)cta * ROWL * WID);
        float4* dst = (float4*)sWl;
        dst[tid] = src[tid];
        dst[tid + NTHR] = src[tid + NTHR];
    }
    {
        const float4* src = (const float4*)(W0 + (size_t)cta * ROWH * XD);
        float4* dst = (float4*)sW0;
        for (int i = tid; i < SM_W0 / 4; i += NTHR) dst[i] = src[i];
    }
    if (tid < ROWH)     sB0[tid] = b0[cta * ROWH + tid];
    if (tid < 3*ROWH) { int l = tid / ROWH, r = tid % ROWH;
                        sBh[tid] = bh[l * WID + cta * ROWH + r]; }
    if (tid < ROWL)     sBl[tid] = bl[cta * ROWL + tid];
    sBetaW[tid] = beta_W[tid];

    const float sc   = scale[0];
    const float bbb  = beta_b[0];
    unsigned gen = *(volatile unsigned*)&g_gen_base;

    // ---- y0 = concat(softmax(y0_log), hvec) ----
    if (tid == 0) {
        float e[NST]; float m = -1e30f;
        for (int i = 0; i < NST; i++) { e[i] = y0_log[i]; m = fmaxf(m, e[i]); }
        float s = 0.f;
        for (int i = 0; i < NST; i++) { e[i] = expf(e[i] - m); s += e[i]; }
        for (int i = 0; i < NST; i++) sY[i] = e[i] / s;
    }
    sY[NST + tid] = hvec[tid];          // NTHR == HID
    __syncthreads();

    if (cta == 0) {
        if (tid < NST) out[tid] = sY[tid];
        out[TLEN * NST + tid] = sY[NST + tid];
    }

    for (int iv = 0; iv < TLEN - 1; iv++) {
        float dt = (ts[iv + 1] - ts[iv]) * (1.0f / SUB);
        #pragma unroll 1
        for (int ss = 0; ss < SUB; ss++) {
            for (int i = tid; i < XD; i += NTHR) { sStage[i] = sY[i]; sKacc[i] = 0.f; }
            __syncthreads();
            #pragma unroll 1
            for (int st = 0; st < 4; st++) {
                // ---------- layer 0 : warp = local row ----------
                {
                    const float* wr = sW0 + wid * XD;
                    float a = 0.f;
                    #pragma unroll
                    for (int k = 0; k < 9; k++) {
                        int c = lane + (k << 5);
                        if (c < XD) {
                            float x = (c < HID) ? sStage[NST + c] : sStage[c - HID];
                            a = fmaf(wr[c], x, a);
                        }
                    }
                    a = wred(a);
                    if (lane == 0)
                        __stcg(&g_z[0][cta * ROWH + wid], sp_f(a + sB0[wid]));
                }
                // ---------- warp 7: SEIR derivative (overlaps barrier) ----------
                if (wid == 7) {
                    float a = 0.f;
                    #pragma unroll
                    for (int m = 0; m < 8; m++)
                        a = fmaf(sBetaW[lane + (m << 5)], sStage[NST + lane + (m << 5)], a);
                    a = wred(a);
                    if (lane == 0) {
                        const float xi = (float)(13.0/12.0), mu = (float)(0.041/12.0);
                        const float sg = (float)(91.0/12.0), nu = (float)(36.0/12.0);
                        const float ga = (float)(1.8/12.0);
                        float bb1 = 8.0f / (1.0f + expf(-(a + bbb))) + 25.0f;
                        float bb2 = 0.5f*bb1, bb3 = 0.35f*bb1, bb4 = 0.25f*bb1;
                        float M  = sStage[0],  S1 = sStage[1],  E1 = sStage[2];
                        float E2 = sStage[3],  E3 = sStage[4],  E4 = sStage[5];
                        float I1 = sStage[6],  I2 = sStage[7],  I3 = sStage[8],  I4 = sStage[9];
                        float R1 = sStage[10], R2 = sStage[11], R3 = sStage[12], R4 = sStage[13];
                        float S2 = sStage[14], S3 = sStage[15], S4 = sStage[16];
                        float I = I1 + I2 + I3 + I4;
                        float R = R1 + R2 + R3 + R4;
                        sKst[0]  = R * mu - (xi + mu) * M;
                        sKst[1]  = mu * (1.0f - R) + xi * M - mu * S1 - bb1 * I * S1;
                        sKst[2]  = bb1 * I * S1 - (mu + sg) * E1;
                        sKst[3]  = bb2 * I * S2 - (mu + sg) * E2;
                        sKst[4]  = bb3 * I * S3 - (mu + sg) * E3;
                        sKst[5]  = bb4 * I * S4 - (mu + sg) * E4;
                        sKst[6]  = sg * E1 - (nu + mu) * I1;
                        sKst[7]  = sg * E2 - (nu + mu) * I2;
                        sKst[8]  = sg * E3 - (nu + mu) * I3;
                        sKst[9]  = sg * E4 - (nu + mu) * I4;
                        sKst[10] = nu * I1 - (mu + ga) * R1;
                        sKst[11] = nu * I2 - (mu + ga) * R2;
                        sKst[12] = nu * I3 - (mu + ga) * R3;
                        sKst[13] = nu * I4 - (mu + ga) * R4;
                        sKst[14] = ga * R1 - mu * S2 - bb2 * I * S2;
                        sKst[15] = ga * R2 - mu * S3 - bb3 * I * S3;
                        sKst[16] = ga * (R3 + R4) - mu * S4 - bb4 * I * S4;
                    }
                }
                ++gen; grid_barrier(gen);

                // ---------- hidden layers ----------
                int buf = 0;
                #pragma unroll 1
                for (int l = 0; l < 3; l++) {
                    ((float4*)sZ)[tid] = __ldcg(((const float4*)g_z[buf]) + tid);
                    __syncthreads();
                    const float4* wr = (const float4*)(sWh + (l * ROWH + wid) * WID);
                    const float4* zz = (const float4*)sZ;
                    float ax = 0.f, ay = 0.f, az = 0.f, aw = 0.f;
                    #pragma unroll
                    for (int k = 0; k < 8; k++) {
                        float4 w4 = wr[lane + (k << 5)];
                        float4 z4 = zz[lane + (k << 5)];
                        ax = fmaf(w4.x, z4.x, ax); ay = fmaf(w4.y, z4.y, ay);
                        az = fmaf(w4.z, z4.z, az); aw = fmaf(w4.w, z4.w, aw);
                    }
                    float a = wred((ax + az) + (ay + aw));
                    if (lane == 0)
                        __stcg(&g_z[buf ^ 1][cta * ROWH + wid],
                               sp_f(a + sBh[l * ROWH + wid]));
                    ++gen; grid_barrier(gen);
                    buf ^= 1;
                }

                // ---------- output layer (2 rows / CTA) ----------
                ((float4*)sZ)[tid] = __ldcg(((const float4*)g_z[buf]) + tid);
                __syncthreads();
                {
                    int r = tid >> 7;          // 0..1
                    int g = tid & 127;
                    const float4* wr = (const float4*)(sWl + r * WID);
                    const float4* zz = (const float4*)sZ;
                    float ax = 0.f, ay = 0.f, az = 0.f, aw = 0.f;
                    #pragma unroll
                    for (int k = 0; k < 2; k++) {
                        float4 w4 = wr[g + (k << 7)];
                        float4 z4 = zz[g + (k << 7)];
                        ax = fmaf(w4.x, z4.x, ax); ay = fmaf(w4.y, z4.y, ay);
                        az = fmaf(w4.z, z4.z, az); aw = fmaf(w4.w, z4.w, aw);
                    }
                    float a = wred((ax + az) + (ay + aw));
                    if (lane == 0) sRed[wid] = a;
                }
                __syncthreads();
                if (tid < ROWL) {
                    float a = sRed[tid*4] + sRed[tid*4+1] + sRed[tid*4+2] + sRed[tid*4+3];
                    __stcg(&g_dh[cta * ROWL + tid], tanhf(0.01f * (a + sBl[tid])));
                }
                ++gen; grid_barrier(gen);

                // ---------- RK4 stage update ----------
                {
                    float w    = (st == 0 || st == 3) ? 1.f : 2.f;
                    float cfac = (st < 2) ? 0.5f * dt : dt;
                    int i = tid;
                    float k = (i < NST) ? sKst[i] : sc * __ldcg(&g_dh[i - NST]);
                    sKacc[i] += w * k;
                    if (st < 3) sStage[i] = fmaf(cfac, k, sY[i]);
                    if (tid < XD - NTHR) {
                        int j = tid + NTHR;
                        float k2 = sc * __ldcg(&g_dh[j - NST]);
                        sKacc[j] += w * k2;
                        if (st < 3) sStage[j] = fmaf(cfac, k2, sY[j]);
                    }
                }
                __syncthreads();
            }
            for (int i = tid; i < XD; i += NTHR)
                sY[i] = fmaf(dt * (1.0f / 6.0f), sKacc[i], sY[i]);
            __syncthreads();
        }
        if (cta == 0) {
            if (tid < NST) out[(iv + 1) * NST + tid] = sY[tid];
            out[TLEN * NST + (iv + 1) * HID + tid] = sY[NST + tid];
        }
    }
    if (cta == 0 && tid == 0)
        *(volatile unsigned*)&g_gen_base = gen;   // keep gen monotonic across replays
}

extern "C" void kernel_launch(void* const* d_in, const int* in_sizes, int n_in,
                              void* d_out, int out_size)
{
    (void)in_sizes; (void)n_in; (void)out_size;
    cudaFuncSetAttribute(ode_kernel, cudaFuncAttributeMaxDynamicSharedMemorySize,
                         SMEM_BYTES);
    ode_kernel<<<NCTA, NTHR, SMEM_BYTES>>>(
        (const float*)d_in[0],   // ts
        (const float*)d_in[1],   // W0
        (const float*)d_in[2],   // b0
        (const float*)d_in[3],   // Wh
        (const float*)d_in[4],   // bh
        (const float*)d_in[5],   // Wl
        (const float*)d_in[6],   // bl
        (const float*)d_in[7],   // beta_W
        (const float*)d_in[8],   // beta_b
        (const float*)d_in[9],   // hvec
        (const float*)d_in[10],  // scale
        (const float*)d_in[11],  // y0_log
        (float*)d_out);
}

// round 3
// speedup vs baseline: 1.8136x; 1.8136x over previous
#include <cuda_runtime.h>
#include <math.h>

#define NCTA 128
#define NTHR 256
#define WID  1024
#define HID  256
#define NST  17
#define XD   273
#define TLEN 64
#define SUB  8
#define ROWH 8          /* hidden rows per CTA  (1024/128) */
#define ROWL 2          /* output rows per CTA  (256/128)  */

#define SM_WH (3*ROWH*WID)     /* 24576 */
#define SM_WL (ROWL*WID)       /* 2048  */
#define SM_W0 (ROWH*XD)        /* 2184  */
#define SMEM_FLOATS (SM_WH + SM_WL + SM_W0 + 3*280 + HID + 8 + 8 + 24 + 4 + 20 + 8 + 8)
#define SMEM_BYTES  (SMEM_FLOATS*4)

// ---------------- global dataflow state ----------------
__device__ __align__(128) float    gz[4][WID];          // z1..z4
__device__ __align__(128) float    gdh[HID];
__device__ __align__(128) unsigned gtag[5*NCTA*32];     // one tag per 128B line
__device__ __align__(128) unsigned g_base;              // monotonic across replays

__device__ __forceinline__ unsigned ld_acq(const unsigned* p)
{
    unsigned v;
    asm volatile("ld.acquire.gpu.global.b32 %0, [%1];" : "=r"(v) : "l"(p) : "memory");
    return v;
}
__device__ __forceinline__ void st_rel(unsigned* p, unsigned v)
{
    asm volatile("st.release.gpu.global.b32 [%0], %1;" :: "l"(p), "r"(v) : "memory");
}

// warp-0 collective: wait until all 128 tags of `slot` reach gen (wrap-safe)
__device__ __forceinline__ void wait_tags(int slot, unsigned gen, int lane)
{
    const unsigned* p = gtag + ((size_t)slot*NCTA + lane)*32;
    for (;;) {
        unsigned a0 = ld_acq(p);
        unsigned a1 = ld_acq(p + 32*32);
        unsigned a2 = ld_acq(p + 64*32);
        unsigned a3 = ld_acq(p + 96*32);
        bool ok = ((int)(a0-gen) >= 0) & ((int)(a1-gen) >= 0) &
                  ((int)(a2-gen) >= 0) & ((int)(a3-gen) >= 0);
        if (__all_sync(0xffffffffu, ok)) break;
    }
}

__device__ __forceinline__ float sp_f(float x)   // softplus
{
    return fmaxf(x, 0.0f) + log1pf(expf(-fabsf(x)));
}

__device__ __forceinline__ float wred(float v)
{
    #pragma unroll
    for (int o = 16; o; o >>= 1) v += __shfl_xor_sync(0xffffffffu, v, o);
    return v;
}

__global__ void __launch_bounds__(NTHR, 1)
ode_kernel(const float* __restrict__ ts, const float* __restrict__ W0,
           const float* __restrict__ b0, const float* __restrict__ Wh,
           const float* __restrict__ bh, const float* __restrict__ Wl,
           const float* __restrict__ bl, const float* __restrict__ beta_W,
           const float* __restrict__ beta_b, const float* __restrict__ hvec,
           const float* __restrict__ scale, const float* __restrict__ y0_log,
           float* __restrict__ out)
{
    extern __shared__ float smem[];
    float* sWh    = smem;               // [3][ROWH][WID]
    float* sWl    = sWh + SM_WH;        // [ROWL][WID]
    float* sW0    = sWl + SM_WL;        // [ROWH][XD]
    float* sY     = sW0 + SM_W0;        // 280
    float* sStage = sY + 280;           // 280
    float* sKacc  = sStage + 280;       // 280
    float* sBetaW = sKacc + 280;        // 256
    float* sOut   = sBetaW + HID;       // 8   (16B aligned)
    float* sB0    = sOut + 8;           // 8
    float* sBh    = sB0 + 8;            // 24
    float* sBl    = sBh + 24;           // 4
    float* sKst   = sBl + 4;            // 20
    float* sRed   = sKst + 20;          // 8
    float* sDh    = sRed + 8;           // 8

    const int tid  = threadIdx.x;
    const int cta  = blockIdx.x;
    const int wid  = tid >> 5;
    const int lane = tid & 31;

    // ---- one-time: weights -> smem ----
    #pragma unroll 1
    for (int l = 0; l < 3; l++) {
        const float4* src = (const float4*)(Wh + ((size_t)l * WID + (size_t)cta * ROWH) * WID);
        float4* dst = (float4*)(sWh + l * ROWH * WID);
        #pragma unroll
        for (int i = 0; i < (ROWH * WID / 4) / NTHR; i++)
            dst[tid + i * NTHR] = src[tid + i * NTHR];
    }
    {
        const float4* src = (const float4*)(Wl + (size_t)cta * ROWL * WID);
        float4* dst = (float4*)sWl;
        dst[tid] = src[tid];
        dst[tid + NTHR] = src[tid + NTHR];
    }
    {
        const float4* src = (const float4*)(W0 + (size_t)cta * ROWH * XD);
        float4* dst = (float4*)sW0;
        for (int i = tid; i < SM_W0 / 4; i += NTHR) dst[i] = src[i];
    }
    if (tid < ROWH)     sB0[tid] = b0[cta * ROWH + tid];
    if (tid < 3*ROWH) { int l = tid / ROWH, r = tid % ROWH;
                        sBh[tid] = bh[l * WID + cta * ROWH + r]; }
    if (tid < ROWL)     sBl[tid] = bl[cta * ROWL + tid];
    sBetaW[tid] = beta_W[tid];

    const float sc  = scale[0];
    const float bbb = beta_b[0];
    unsigned gen = __ldcg(&g_base);

    // ---- y0 = concat(softmax(y0_log), hvec) ----
    if (tid == 0) {
        float e[NST]; float m = -1e30f;
        for (int i = 0; i < NST; i++) { e[i] = y0_log[i]; m = fmaxf(m, e[i]); }
        float s = 0.f;
        for (int i = 0; i < NST; i++) { e[i] = expf(e[i] - m); s += e[i]; }
        for (int i = 0; i < NST; i++) sY[i] = e[i] / s;
    }
    sY[NST + tid] = hvec[tid];
    __syncthreads();

    if (cta == 0) {
        if (tid < NST) out[tid] = sY[tid];
        out[TLEN * NST + tid] = sY[NST + tid];
    }

    for (int iv = 0; iv < TLEN - 1; iv++) {
        float dt = (ts[iv + 1] - ts[iv]) * (1.0f / SUB);
        #pragma unroll 1
        for (int ss = 0; ss < SUB; ss++) {
            for (int i = tid; i < XD; i += NTHR) { sStage[i] = sY[i]; sKacc[i] = 0.f; }
            __syncthreads();
            #pragma unroll 1
            for (int st = 0; st < 4; st++) {
                // ---------- layer 0 : warp = local row ----------
                {
                    const float* wr = sW0 + wid * XD;
                    float a = 0.f;
                    #pragma unroll
                    for (int k = 0; k < 9; k++) {
                        int c = lane + (k << 5);
                        if (c < XD) {
                            float x = (c < HID) ? sStage[NST + c] : sStage[c - HID];
                            a = fmaf(wr[c], x, a);
                        }
                    }
                    a = wred(a);
                    if (lane == 0) sOut[wid] = sp_f(a + sB0[wid]);
                }
                __syncthreads();
                ++gen;
                if (tid == 0) {
                    float4* dst = (float4*)&gz[0][cta * ROWH];
                    __stcg(dst,     *(float4*)sOut);
                    __stcg(dst + 1, *(float4*)(sOut + 4));
                    st_rel(&gtag[(size_t)cta * 32], gen);
                }
                // warp 1: SEIR derivative overlapped with warp-0 polling
                if (wid == 1) {
                    float a = 0.f;
                    #pragma unroll
                    for (int m = 0; m < 8; m++)
                        a = fmaf(sBetaW[lane + (m << 5)], sStage[NST + lane + (m << 5)], a);
                    a = wred(a);
                    if (lane == 0) {
                        const float xi = (float)(13.0/12.0), mu = (float)(0.041/12.0);
                        const float sg = (float)(91.0/12.0), nu = (float)(36.0/12.0);
                        const float ga = (float)(1.8/12.0);
                        float bb1 = 8.0f / (1.0f + expf(-(a + bbb))) + 25.0f;
                        float bb2 = 0.5f*bb1, bb3 = 0.35f*bb1, bb4 = 0.25f*bb1;
                        float M  = sStage[0],  S1 = sStage[1],  E1 = sStage[2];
                        float E2 = sStage[3],  E3 = sStage[4],  E4 = sStage[5];
                        float I1 = sStage[6],  I2 = sStage[7],  I3 = sStage[8],  I4 = sStage[9];
                        float R1 = sStage[10], R2 = sStage[11], R3 = sStage[12], R4 = sStage[13];
                        float S2 = sStage[14], S3 = sStage[15], S4 = sStage[16];
                        float I = I1 + I2 + I3 + I4;
                        float R = R1 + R2 + R3 + R4;
                        sKst[0]  = R * mu - (xi + mu) * M;
                        sKst[1]  = mu * (1.0f - R) + xi * M - mu * S1 - bb1 * I * S1;
                        sKst[2]  = bb1 * I * S1 - (mu + sg) * E1;
                        sKst[3]  = bb2 * I * S2 - (mu + sg) * E2;
                        sKst[4]  = bb3 * I * S3 - (mu + sg) * E3;
                        sKst[5]  = bb4 * I * S4 - (mu + sg) * E4;
                        sKst[6]  = sg * E1 - (nu + mu) * I1;
                        sKst[7]  = sg * E2 - (nu + mu) * I2;
                        sKst[8]  = sg * E3 - (nu + mu) * I3;
                        sKst[9]  = sg * E4 - (nu + mu) * I4;
                        sKst[10] = nu * I1 - (mu + ga) * R1;
                        sKst[11] = nu * I2 - (mu + ga) * R2;
                        sKst[12] = nu * I3 - (mu + ga) * R3;
                        sKst[13] = nu * I4 - (mu + ga) * R4;
                        sKst[14] = ga * R1 - mu * S2 - bb2 * I * S2;
                        sKst[15] = ga * R2 - mu * S3 - bb3 * I * S3;
                        sKst[16] = ga * (R3 + R4) - mu * S4 - bb4 * I * S4;
                    }
                }
                if (wid == 0) wait_tags(0, gen, lane);
                __syncthreads();

                // ---------- hidden layers ----------
                #pragma unroll 1
                for (int l = 0; l < 3; l++) {
                    const float4* zsrc = (const float4*)gz[l];
                    float4 zr[8];
                    #pragma unroll
                    for (int k = 0; k < 8; k++) zr[k] = __ldcg(zsrc + lane + (k << 5));
                    const float4* wr = (const float4*)(sWh + (l * ROWH + wid) * WID);
                    float ax = 0.f, ay = 0.f, az = 0.f, aw = 0.f;
                    #pragma unroll
                    for (int k = 0; k < 8; k++) {
                        float4 w4 = wr[lane + (k << 5)];
                        ax = fmaf(w4.x, zr[k].x, ax); ay = fmaf(w4.y, zr[k].y, ay);
                        az = fmaf(w4.z, zr[k].z, az); aw = fmaf(w4.w, zr[k].w, aw);
                    }
                    float a = wred((ax + az) + (ay + aw));
                    if (lane == 0) sOut[wid] = sp_f(a + sBh[l * ROWH + wid]);
                    __syncthreads();
                    ++gen;
                    if (tid == 0) {
                        float4* dst = (float4*)&gz[l + 1][cta * ROWH];
                        __stcg(dst,     *(float4*)sOut);
                        __stcg(dst + 1, *(float4*)(sOut + 4));
                        st_rel(&gtag[((size_t)(l + 1) * NCTA + cta) * 32], gen);
                    }
                    if (wid == 0) wait_tags(l + 1, gen, lane);
                    __syncthreads();
                }

                // ---------- output layer (2 rows / CTA, 4 warps each) ----------
                {
                    int r = tid >> 7;
                    int g = tid & 127;
                    const float4* zsrc = (const float4*)gz[3];
                    float4 z0 = __ldcg(zsrc + g);
                    float4 z1 = __ldcg(zsrc + g + 128);
                    const float4* wr = (const float4*)(sWl + r * WID);
                    float4 w0 = wr[g];
                    float4 w1 = wr[g + 128];
                    float ax = fmaf(w0.x, z0.x, w1.x * z1.x);
                    float ay = fmaf(w0.y, z0.y, w1.y * z1.y);
                    float az = fmaf(w0.z, z0.z, w1.z * z1.z);
                    float aw = fmaf(w0.w, z0.w, w1.w * z1.w);
                    float a = wred((ax + az) + (ay + aw));
                    if (lane == 0) sRed[wid] = a;
                }
                __syncthreads();
                if (tid < ROWL) {
                    float a = sRed[tid*4] + sRed[tid*4+1] + sRed[tid*4+2] + sRed[tid*4+3];
                    sDh[tid] = tanhf(0.01f * (a + sBl[tid]));
                }
                __syncthreads();
                ++gen;
                if (tid == 0) {
                    __stcg(&gdh[cta * ROWL],     sDh[0]);
                    __stcg(&gdh[cta * ROWL + 1], sDh[1]);
                    st_rel(&gtag[((size_t)4 * NCTA + cta) * 32], gen);
                }
                if (wid == 0) wait_tags(4, gen, lane);
                __syncthreads();

                // ---------- RK4 stage update ----------
                {
                    float w    = (st == 0 || st == 3) ? 1.f : 2.f;
                    float cfac = (st < 2) ? 0.5f * dt : dt;
                    int i = tid;
                    float k = (i < NST) ? sKst[i] : sc * __ldcg(&gdh[i - NST]);
                    sKacc[i] += w * k;
                    if (st < 3) sStage[i] = fmaf(cfac, k, sY[i]);
                    if (tid < XD - NTHR) {
                        int j = tid + NTHR;
                        float k2 = sc * __ldcg(&gdh[j - NST]);
                        sKacc[j] += w * k2;
                        if (st < 3) sStage[j] = fmaf(cfac, k2, sY[j]);
                    }
                }
                __syncthreads();
            }
            for (int i = tid; i < XD; i += NTHR)
                sY[i] = fmaf(dt * (1.0f / 6.0f), sKacc[i], sY[i]);
            __syncthreads();
        }
        if (cta == 0) {
            if (tid < NST) out[(iv + 1) * NST + tid] = sY[tid];
            out[TLEN * NST + (iv + 1) * HID + tid] = sY[NST + tid];
        }
    }
    if (cta == 0 && tid == 0)
        *(volatile unsigned*)&g_base = gen;   // keep tags monotonic across replays
}

extern "C" void kernel_launch(void* const* d_in, const int* in_sizes, int n_in,
                              void* d_out, int out_size)
{
    (void)in_sizes; (void)n_in; (void)out_size;
    cudaFuncSetAttribute(ode_kernel, cudaFuncAttributeMaxDynamicSharedMemorySize,
                         SMEM_BYTES);
    ode_kernel<<<NCTA, NTHR, SMEM_BYTES>>>(
        (const float*)d_in[0],   // ts
        (const float*)d_in[1],   // W0
        (const float*)d_in[2],   // b0
        (const float*)d_in[3],   // Wh
        (const float*)d_in[4],   // bh
        (const float*)d_in[5],   // Wl
        (const float*)d_in[6],   // bl
        (const float*)d_in[7],   // beta_W
        (const float*)d_in[8],   // beta_b
        (const float*)d_in[9],   // hvec
        (const float*)d_in[10],  // scale
        (const float*)d_in[11],  // y0_log
        (float*)d_out);
}